// round 16
// baseline (speedup 1.0000x reference)
#include <cuda_runtime.h>
#include <cuda_bf16.h>
#include <math.h>
#include <stdint.h>

// Problem constants (fixed by the dataset): N=50000, E=800000, F=256, H=4, C=128
#define NMAX 50048
#define EPMAX 850048   // E + N self-loops

// ---- static scratch (no allocations allowed) ----
__device__ float g_buf0[(size_t)NMAX * 512];          // GEMM output h (fp32)
__device__ __nv_bfloat16 g_ahi[(size_t)NMAX * 512];   // activation hi
__device__ __nv_bfloat16 g_alo[(size_t)NMAX * 512];   // activation lo
__device__ __nv_bfloat16 g_whi[512 * 512];            // weight hi
__device__ __nv_bfloat16 g_wlo[512 * 512];            // weight lo
__device__ float g_sn[NMAX * 4];
__device__ float g_dn[NMAX * 4];
__device__ int   g_deg[NMAX];
__device__ int   g_off[NMAX + 1];
__device__ int   g_cur[NMAX];
__device__ int   g_csr_src[EPMAX];
__device__ int   g_is32;

// ================= helpers =================
__device__ __forceinline__ uint32_t smem_u32(const void* p) {
    uint32_t a;
    asm("{ .reg .u64 t; cvta.to.shared.u64 t, %1; cvt.u32.u64 %0, t; }" : "=r"(a) : "l"(p));
    return a;
}
__device__ __forceinline__ void ldsm4(uint32_t* r, uint32_t addr) {
    asm volatile("ldmatrix.sync.aligned.m8n8.x4.shared.b16 {%0,%1,%2,%3}, [%4];"
        : "=r"(r[0]), "=r"(r[1]), "=r"(r[2]), "=r"(r[3]) : "r"(addr));
}
__device__ __forceinline__ void mma16816(float* c, const uint32_t* a, const uint32_t* b) {
    asm volatile("mma.sync.aligned.m16n8k16.row.col.f32.bf16.bf16.f32 "
        "{%0,%1,%2,%3}, {%4,%5,%6,%7}, {%8,%9}, {%0,%1,%2,%3};"
        : "+f"(c[0]), "+f"(c[1]), "+f"(c[2]), "+f"(c[3])
        : "r"(a[0]), "r"(a[1]), "r"(a[2]), "r"(a[3]), "r"(b[0]), "r"(b[1]));
}
__device__ __forceinline__ uint32_t pack2(__nv_bfloat16 a, __nv_bfloat16 b) {
    return (uint32_t)__bfloat16_as_ushort(a) | ((uint32_t)__bfloat16_as_ushort(b) << 16);
}
__device__ __forceinline__ void cp16(uint32_t dst, const void* src, int sz) {
    asm volatile("cp.async.cg.shared.global [%0], [%1], 16, %2;"
                 :: "r"(dst), "l"(src), "r"(sz) : "memory");
}
#define CP_COMMIT asm volatile("cp.async.commit_group;" ::: "memory")
#define CP_WAIT1  asm volatile("cp.async.wait_group 1;" ::: "memory")

// ---- fp32 -> (hi,lo) bf16 split, elementwise (n % 4 == 0) ----
__global__ void split_kernel(const float* __restrict__ in,
                             __nv_bfloat16* __restrict__ hi,
                             __nv_bfloat16* __restrict__ lo, int n)
{
    int i = (blockIdx.x * blockDim.x + threadIdx.x) * 4;
    if (i >= n) return;
    float4 v = *(const float4*)(in + i);
    __nv_bfloat16 h0 = __float2bfloat16(v.x), h1 = __float2bfloat16(v.y);
    __nv_bfloat16 h2 = __float2bfloat16(v.z), h3 = __float2bfloat16(v.w);
    uint2 hw = make_uint2(pack2(h0, h1), pack2(h2, h3));
    uint2 lw = make_uint2(
        pack2(__float2bfloat16(v.x - __bfloat162float(h0)),
              __float2bfloat16(v.y - __bfloat162float(h1))),
        pack2(__float2bfloat16(v.z - __bfloat162float(h2)),
              __float2bfloat16(v.w - __bfloat162float(h3))));
    *(uint2*)(hi + i) = hw;
    *(uint2*)(lo + i) = lw;
}

// ================= bf16 HMMA GEMM, 3-stage cp.async pipeline =================
// SMEM stage: Ahi[128][32] @0, Alo @8192, Bhi @16384, Blo @24576 (bf16, 64B rows)
// Swizzle: 16B chunk (r, g) stored at col (g ^ ((r>>1)&3)) -> conflict-free LDSM.
#define STAGE_BYTES 32768
#define NSTAGES 3
#define GSMEM_BYTES (NSTAGES * STAGE_BYTES)
#define SWOFF(r, g) ((uint32_t)((r) * 64 + (((g) ^ (((r) >> 1) & 3)) * 16)))

// Y[N,M] = A[N,K] @ B[M,K]^T with A=Ahi+Alo, B=Bhi+Blo (drop lo*lo).
// Fused epilogue also computes sn/dn dots for the head == column tile.
// K % 32 == 0, K/32 >= 3; M % 128 == 0; gridDim.y == Hheads. 256 threads.
__global__ __launch_bounds__(256) void gemm_bf16(
    const __nv_bfloat16* __restrict__ Ahi, const __nv_bfloat16* __restrict__ Alo,
    const __nv_bfloat16* __restrict__ Bhi, const __nv_bfloat16* __restrict__ Blo,
    float* __restrict__ Y, int Nrows, int K, int Mout,
    const float* __restrict__ Asrc, const float* __restrict__ Adst,
    float* __restrict__ snv, float* __restrict__ dnv, int Hheads)
{
    extern __shared__ char smem[];
    const int tid = threadIdx.x, lane = tid & 31, wid = tid >> 5;
    const int wm = wid >> 2, wn = wid & 3;          // warp grid 2 x 4
    const int rowBase = blockIdx.x * 128, colBase = blockIdx.y * 128;
    const uint32_t sb = smem_u32(smem);

    float c[4][4][4];
#pragma unroll
    for (int i = 0; i < 4; i++)
#pragma unroll
        for (int j = 0; j < 4; j++)
#pragma unroll
            for (int q = 0; q < 4; q++) c[i][j][q] = 0.f;

    const int NC = K >> 5;

#define LOADST(BUF, K0) do {                                                   \
    uint32_t st = sb + (BUF) * STAGE_BYTES;                                    \
    _Pragma("unroll")                                                          \
    for (int it = 0; it < 2; it++) {                                           \
        int chunk = it * 256 + tid;                                            \
        int r = chunk >> 2, g = chunk & 3;                                     \
        uint32_t soff = SWOFF(r, g);                                           \
        int gr = rowBase + r;                                                  \
        int sz = (gr < Nrows) ? 16 : 0;                                        \
        int grc = gr < Nrows ? gr : (Nrows - 1);                               \
        cp16(st + soff,         Ahi + (size_t)grc * K + (K0) + g * 8, sz);     \
        cp16(st + 8192 + soff,  Alo + (size_t)grc * K + (K0) + g * 8, sz);     \
        cp16(st + 16384 + soff, Bhi + (size_t)(colBase + r) * K + (K0) + g * 8, 16); \
        cp16(st + 24576 + soff, Blo + (size_t)(colBase + r) * K + (K0) + g * 8, 16); \
    }                                                                          \
} while (0)

    const int lrow = lane & 15, lsel = lane >> 4;

#define COMPUTE(BUF) do {                                                      \
    uint32_t ab = sb + (BUF) * STAGE_BYTES;                                    \
    _Pragma("unroll")                                                          \
    for (int ks = 0; ks < 2; ks++) {                                           \
        int g = ks * 2 + lsel;                                                 \
        uint32_t ahi[4][4], alo[4][4];                                         \
        _Pragma("unroll")                                                      \
        for (int mt = 0; mt < 4; mt++) {                                       \
            int row = wm * 64 + mt * 16 + lrow;                                \
            uint32_t off = SWOFF(row, g);                                      \
            ldsm4(ahi[mt], ab + off);                                          \
            ldsm4(alo[mt], ab + 8192 + off);                                   \
        }                                                                      \
        uint32_t bhi[2][4], blo[2][4];                                         \
        _Pragma("unroll")                                                      \
        for (int bt = 0; bt < 2; bt++) {                                       \
            int row = wn * 32 + bt * 16 + lrow;                                \
            uint32_t off = SWOFF(row, g);                                      \
            ldsm4(bhi[bt], ab + 16384 + off);                                  \
            ldsm4(blo[bt], ab + 24576 + off);                                  \
        }                                                                      \
        _Pragma("unroll")                                                      \
        for (int mt = 0; mt < 4; mt++)                                         \
        _Pragma("unroll")                                                      \
        for (int nt = 0; nt < 4; nt++) {                                       \
            uint32_t bh[2] = { bhi[nt >> 1][nt & 1], bhi[nt >> 1][(nt & 1) + 2] }; \
            uint32_t bl[2] = { blo[nt >> 1][nt & 1], blo[nt >> 1][(nt & 1) + 2] }; \
            mma16816(c[mt][nt], ahi[mt], bh);                                  \
            mma16816(c[mt][nt], ahi[mt], bl);                                  \
            mma16816(c[mt][nt], alo[mt], bh);                                  \
        }                                                                      \
    }                                                                          \
} while (0)

    LOADST(0, 0);  CP_COMMIT;
    LOADST(1, 32); CP_COMMIT;

    for (int cc = 0; cc < NC; cc++) {
        CP_WAIT1;
        __syncthreads();
        int nx = cc + 2;
        if (nx < NC) LOADST(nx % 3, nx * 32);
        CP_COMMIT;
        COMPUTE(cc % 3);
    }

    // ---- epilogue 1: C fragment -> Y (fp32) ----
#pragma unroll
    for (int mt = 0; mt < 4; mt++) {
        int r0 = rowBase + wm * 64 + mt * 16 + (lane >> 2);
        int r1 = r0 + 8;
#pragma unroll
        for (int nt = 0; nt < 4; nt++) {
            int col = colBase + wn * 32 + nt * 8 + (lane & 3) * 2;
            if (r0 < Nrows)
                *(float2*)(Y + (size_t)r0 * Mout + col) = make_float2(c[mt][nt][0], c[mt][nt][1]);
            if (r1 < Nrows)
                *(float2*)(Y + (size_t)r1 * Mout + col) = make_float2(c[mt][nt][2], c[mt][nt][3]);
        }
    }

    // ---- epilogue 2: fused sn/dn dots (head == column tile) ----
    int hh = blockIdx.y;
    const float* asv = Asrc + hh * 128;
    const float* adv = Adst + hh * 128;
    float* sred = (float*)smem;              // [128 rows][2]
    __syncthreads();                         // mainloop smem reads done
    if (tid < 128) { sred[tid * 2] = 0.f; sred[tid * 2 + 1] = 0.f; }
    __syncthreads();

    float as[8], ad[8];
#pragma unroll
    for (int nt = 0; nt < 4; nt++)
#pragma unroll
        for (int j = 0; j < 2; j++) {
            int cidx = wn * 32 + nt * 8 + (lane & 3) * 2 + j;
            as[nt * 2 + j] = asv[cidx];
            ad[nt * 2 + j] = adv[cidx];
        }
#pragma unroll
    for (int mt = 0; mt < 4; mt++) {
        float s0 = 0.f, d0 = 0.f, s1 = 0.f, d1 = 0.f;
#pragma unroll
        for (int nt = 0; nt < 4; nt++)
#pragma unroll
            for (int j = 0; j < 2; j++) {
                float a = as[nt * 2 + j], b = ad[nt * 2 + j];
                s0 += c[mt][nt][j] * a;     d0 += c[mt][nt][j] * b;
                s1 += c[mt][nt][2 + j] * a; d1 += c[mt][nt][2 + j] * b;
            }
#pragma unroll
        for (int o = 1; o <= 2; o <<= 1) {
            s0 += __shfl_xor_sync(0xffffffffu, s0, o);
            d0 += __shfl_xor_sync(0xffffffffu, d0, o);
            s1 += __shfl_xor_sync(0xffffffffu, s1, o);
            d1 += __shfl_xor_sync(0xffffffffu, d1, o);
        }
        if ((lane & 3) == 0) {
            int lr = wm * 64 + mt * 16 + (lane >> 2);
            atomicAdd(&sred[lr * 2],           s0);
            atomicAdd(&sred[lr * 2 + 1],       d0);
            atomicAdd(&sred[(lr + 8) * 2],     s1);
            atomicAdd(&sred[(lr + 8) * 2 + 1], d1);
        }
    }
    __syncthreads();
    if (tid < 128) {
        int gr = rowBase + tid;
        if (gr < Nrows) {
            snv[gr * Hheads + hh] = sred[tid * 2];
            dnv[gr * Hheads + hh] = sred[tid * 2 + 1];
        }
    }
}

// ================= graph / CSR machinery (unchanged, known good) =================
__global__ void detect_idx_kernel(const unsigned int* __restrict__ w) {
    int is32 = 0;
#pragma unroll
    for (int i = 1; i < 64; i += 2)
        if (w[i] != 0u) is32 = 1;
    g_is32 = is32;
}
__device__ __forceinline__ int edge_src(const void* ei, int E, int e) {
    return g_is32 ? ((const int*)ei)[e] : (int)((const long long*)ei)[e];
}
__device__ __forceinline__ int edge_dst(const void* ei, int E, int e) {
    return g_is32 ? ((const int*)ei)[E + e] : (int)((const long long*)ei)[E + e];
}
__global__ void hist_kernel(const void* __restrict__ ei, int E, int Nn, int* __restrict__ deg) {
    int e = blockIdx.x * blockDim.x + threadIdx.x;
    int EP = E + Nn;
    if (e >= EP) return;
    int dst = (e < E) ? edge_dst(ei, E, e) : (e - E);
    atomicAdd(&deg[dst], 1);
}
__global__ __launch_bounds__(1024) void scan_kernel(
    const int* __restrict__ deg, int* __restrict__ off, int* __restrict__ cur, int Nn)
{
    __shared__ int wsum[32];
    int tid = threadIdx.x, lane = tid & 31, wid = tid >> 5;
    int chunk = (Nn + 1023) >> 10;
    int start = min(tid * chunk, Nn), end = min(start + chunk, Nn);
    int s = 0;
    for (int i = start; i < end; i++) s += deg[i];
    int v = s;
#pragma unroll
    for (int o = 1; o < 32; o <<= 1) {
        int u = __shfl_up_sync(0xffffffffu, v, o);
        if (lane >= o) v += u;
    }
    if (lane == 31) wsum[wid] = v;
    __syncthreads();
    if (wid == 0) {
        int w = wsum[lane];
#pragma unroll
        for (int o = 1; o < 32; o <<= 1) {
            int u = __shfl_up_sync(0xffffffffu, w, o);
            if (lane >= o) w += u;
        }
        wsum[lane] = w;
    }
    __syncthreads();
    int incl = v + (wid ? wsum[wid - 1] : 0);
    int pre = incl - s;
    for (int i = start; i < end; i++) { off[i] = pre; cur[i] = pre; pre += deg[i]; }
    if (end == Nn) off[Nn] = pre;
}
__global__ void scatter_kernel(const void* __restrict__ ei, int E, int Nn,
                               int* __restrict__ cur, int* __restrict__ srcs)
{
    int e = blockIdx.x * blockDim.x + threadIdx.x;
    int EP = E + Nn;
    if (e >= EP) return;
    int src, dst;
    if (e < E) { src = edge_src(ei, E, e); dst = edge_dst(ei, E, e); }
    else       { src = e - E; dst = src; }
    int pos = atomicAdd(&cur[dst], 1);
    srcs[pos] = src;
}

// ---------------- fused GAT aggregation (H=4), bf16-split output ----------------
__global__ __launch_bounds__(128) void gat_agg_h4(
    const float* __restrict__ h, const float* __restrict__ sn,
    const float* __restrict__ dn, const int* __restrict__ off,
    const int* __restrict__ srcs, const float* __restrict__ bias,
    __nv_bfloat16* __restrict__ ohi, __nv_bfloat16* __restrict__ olo, int Nn)
{
    int n = blockIdx.x;
    int t = threadIdx.x, w = t >> 5, lane = t & 31;
    int beg = off[n], end = off[n + 1];
    float dn_w = dn[n * 4 + w];
    float den = 0.f;
    for (int i = beg + lane; i < end; i += 32) {
        float e = sn[srcs[i] * 4 + w] + dn_w;
        e = e > 0.f ? e : 0.2f * e;
        den += __expf(e);
    }
#pragma unroll
    for (int o = 16; o; o >>= 1) den += __shfl_xor_sync(0xffffffffu, den, o);
    float inv = 1.f / (den + 1e-16f);
    float4 acc = make_float4(0.f, 0.f, 0.f, 0.f);
    for (int i = beg; i < end; i++) {
        int s = srcs[i];
        float e = sn[s * 4 + w] + dn_w;
        e = e > 0.f ? e : 0.2f * e;
        float alpha = __expf(e) * inv;
        float4 v = *((const float4*)(h + (size_t)s * 512) + t);
        acc.x += alpha * v.x; acc.y += alpha * v.y;
        acc.z += alpha * v.z; acc.w += alpha * v.w;
    }
    float4 b = *((const float4*)bias + t);
    acc.x += b.x; acc.y += b.y; acc.z += b.z; acc.w += b.w;
    acc.x = acc.x > 0.f ? acc.x : expm1f(acc.x);
    acc.y = acc.y > 0.f ? acc.y : expm1f(acc.y);
    acc.z = acc.z > 0.f ? acc.z : expm1f(acc.z);
    acc.w = acc.w > 0.f ? acc.w : expm1f(acc.w);
    __nv_bfloat16 h0 = __float2bfloat16(acc.x), h1 = __float2bfloat16(acc.y);
    __nv_bfloat16 h2 = __float2bfloat16(acc.z), h3 = __float2bfloat16(acc.w);
    uint2 hw = make_uint2(pack2(h0, h1), pack2(h2, h3));
    uint2 lw = make_uint2(
        pack2(__float2bfloat16(acc.x - __bfloat162float(h0)),
              __float2bfloat16(acc.y - __bfloat162float(h1))),
        pack2(__float2bfloat16(acc.z - __bfloat162float(h2)),
              __float2bfloat16(acc.w - __bfloat162float(h3))));
    *(uint2*)(ohi + (size_t)n * 512 + t * 4) = hw;
    *(uint2*)(olo + (size_t)n * 512 + t * 4) = lw;
}

// ---------------- fused GAT aggregation (H=1), fp32 output ----------------
__global__ __launch_bounds__(128) void gat_agg_h1(
    const float* __restrict__ h, const float* __restrict__ sn,
    const float* __restrict__ dn, const int* __restrict__ off,
    const int* __restrict__ srcs, const float* __restrict__ bias,
    float* __restrict__ out, int Nn)
{
    int n = blockIdx.x;
    int t = threadIdx.x, lane = t & 31;
    int beg = off[n], end = off[n + 1];
    float dnv = dn[n];
    float den = 0.f;
    for (int i = beg + lane; i < end; i += 32) {
        float e = sn[srcs[i]] + dnv;
        e = e > 0.f ? e : 0.2f * e;
        den += __expf(e);
    }
#pragma unroll
    for (int o = 16; o; o >>= 1) den += __shfl_xor_sync(0xffffffffu, den, o);
    float inv = 1.f / (den + 1e-16f);
    float acc = 0.f;
    for (int i = beg; i < end; i++) {
        int s = srcs[i];
        float e = sn[s] + dnv;
        e = e > 0.f ? e : 0.2f * e;
        float alpha = __expf(e) * inv;
        acc += alpha * h[(size_t)s * 128 + t];
    }
    out[(size_t)n * 128 + t] = acc + bias[t];
}

// ---------------- allocation head ----------------
__global__ __launch_bounds__(64) void head_kernel(
    const float* __restrict__ emb, const float* __restrict__ Wh1,
    const float* __restrict__ bh1, const float* __restrict__ Wh2,
    const float* __restrict__ bh2, float* __restrict__ score, int Nn)
{
    int n = blockIdx.x;
    int t = threadIdx.x;
    __shared__ __align__(16) float se[128];
    __shared__ float sred2[2];
    ((float2*)se)[t] = ((const float2*)(emb + (size_t)n * 128))[t];
    __syncthreads();
    float z = bh1[t];
    const float* wrow = Wh1 + t * 128;
#pragma unroll 8
    for (int k = 0; k < 128; k++) z += se[k] * wrow[k];
    z = fmaxf(z, 0.f);
    float val = z * Wh2[t];
#pragma unroll
    for (int o = 16; o; o >>= 1) val += __shfl_down_sync(0xffffffffu, val, o);
    if ((t & 31) == 0) sred2[t >> 5] = val;
    __syncthreads();
    if (t == 0) {
        float s = sred2[0] + sred2[1] + bh2[0];
        score[n] = 1.f / (1.f + __expf(-s));
    }
}

// ---------------- driver ----------------
extern "C" void kernel_launch(void* const* d_in, const int* in_sizes, int n_in,
                              void* d_out, int out_size)
{
    const float* x      = (const float*)d_in[0];
    const void*  ei     = d_in[1];
    const float* W1     = (const float*)d_in[2];
    const float* a_src1 = (const float*)d_in[3];
    const float* a_dst1 = (const float*)d_in[4];
    const float* b1     = (const float*)d_in[5];
    const float* W2     = (const float*)d_in[6];
    const float* a_src2 = (const float*)d_in[7];
    const float* a_dst2 = (const float*)d_in[8];
    const float* b2     = (const float*)d_in[9];
    const float* W3     = (const float*)d_in[10];
    const float* a_src3 = (const float*)d_in[11];
    const float* a_dst3 = (const float*)d_in[12];
    const float* b3     = (const float*)d_in[13];
    const float* Wh1    = (const float*)d_in[14];
    const float* bh1    = (const float*)d_in[15];
    const float* Wh2    = (const float*)d_in[16];
    const float* bh2    = (const float*)d_in[17];

    int Nn = in_sizes[0] / 256;
    int E  = in_sizes[1] / 2;
    int EP = E + Nn;

    float *buf0, *sn, *dn;
    __nv_bfloat16 *ahi, *alo, *whi, *wlo;
    int *deg, *off, *cur, *srcs;
    cudaGetSymbolAddress((void**)&buf0, g_buf0);
    cudaGetSymbolAddress((void**)&ahi,  g_ahi);
    cudaGetSymbolAddress((void**)&alo,  g_alo);
    cudaGetSymbolAddress((void**)&whi,  g_whi);
    cudaGetSymbolAddress((void**)&wlo,  g_wlo);
    cudaGetSymbolAddress((void**)&sn,   g_sn);
    cudaGetSymbolAddress((void**)&dn,   g_dn);
    cudaGetSymbolAddress((void**)&deg,  g_deg);
    cudaGetSymbolAddress((void**)&off,  g_off);
    cudaGetSymbolAddress((void**)&cur,  g_cur);
    cudaGetSymbolAddress((void**)&srcs, g_csr_src);

    float* out_emb   = (float*)d_out;
    float* out_score = (float*)d_out + (size_t)Nn * 128;

    cudaFuncSetAttribute(gemm_bf16, cudaFuncAttributeMaxDynamicSharedMemorySize, GSMEM_BYTES);

    // ---- CSR build ----
    detect_idx_kernel<<<1, 1>>>((const unsigned int*)ei);
    cudaMemsetAsync(deg, 0, Nn * sizeof(int));
    hist_kernel<<<(EP + 255) / 256, 256>>>(ei, E, Nn, deg);
    scan_kernel<<<1, 1024>>>(deg, off, cur, Nn);
    scatter_kernel<<<(EP + 255) / 256, 256>>>(ei, E, Nn, cur, srcs);

    int rowTiles = (Nn + 127) / 128;

    // ---- Layer 1: 256 -> 512 (sndn fused in GEMM epilogue) ----
    split_kernel<<<(Nn * 256 / 4 + 255) / 256, 256>>>(x, ahi, alo, Nn * 256);
    split_kernel<<<(512 * 256 / 4 + 255) / 256, 256>>>(W1, whi, wlo, 512 * 256);
    gemm_bf16<<<dim3(rowTiles, 4), 256, GSMEM_BYTES>>>(ahi, alo, whi, wlo, buf0, Nn, 256, 512,
                                                       a_src1, a_dst1, sn, dn, 4);
    gat_agg_h4<<<Nn, 128>>>(buf0, sn, dn, off, srcs, b1, ahi, alo, Nn);

    // ---- Layer 2: 512 -> 512 ----
    split_kernel<<<(512 * 512 / 4 + 255) / 256, 256>>>(W2, whi, wlo, 512 * 512);
    gemm_bf16<<<dim3(rowTiles, 4), 256, GSMEM_BYTES>>>(ahi, alo, whi, wlo, buf0, Nn, 512, 512,
                                                       a_src2, a_dst2, sn, dn, 4);
    gat_agg_h4<<<Nn, 128>>>(buf0, sn, dn, off, srcs, b2, ahi, alo, Nn);

    // ---- Layer 3: 512 -> 128 ----
    split_kernel<<<(128 * 512 / 4 + 255) / 256, 256>>>(W3, whi, wlo, 128 * 512);
    gemm_bf16<<<dim3(rowTiles, 1), 256, GSMEM_BYTES>>>(ahi, alo, whi, wlo, buf0, Nn, 512, 128,
                                                       a_src3, a_dst3, sn, dn, 1);
    gat_agg_h1<<<Nn, 128>>>(buf0, sn, dn, off, srcs, b3, out_emb, Nn);

    // ---- Allocation head ----
    head_kernel<<<Nn, 64>>>(out_emb, Wh1, bh1, Wh2, bh2, out_score, Nn);
}

// round 17
// speedup vs baseline: 1.5645x; 1.5645x over previous
#include <cuda_runtime.h>
#include <cuda_bf16.h>
#include <math.h>
#include <stdint.h>

// Problem constants (fixed by the dataset): N=50000, E=800000, F=256, H=4, C=128
#define NMAX 50048
#define EPMAX 850048   // E + N self-loops

// ---- static scratch (no allocations allowed) ----
__device__ float g_buf0[(size_t)NMAX * 512];          // GEMM output h (fp32)
__device__ __nv_bfloat16 g_ahi[(size_t)NMAX * 512];   // activation hi
__device__ __nv_bfloat16 g_alo[(size_t)NMAX * 512];   // activation lo
__device__ __nv_bfloat16 g_whi[512 * 512];            // weight hi
__device__ __nv_bfloat16 g_wlo[512 * 512];            // weight lo
__device__ float g_sn[NMAX * 4];
__device__ float g_dn[NMAX * 4];
__device__ int   g_deg[NMAX];
__device__ int   g_off[NMAX + 1];
__device__ int   g_cur[NMAX];
__device__ int   g_csr_src[EPMAX];
__device__ int   g_is32;

// ================= helpers =================
__device__ __forceinline__ uint32_t smem_u32(const void* p) {
    uint32_t a;
    asm("{ .reg .u64 t; cvta.to.shared.u64 t, %1; cvt.u32.u64 %0, t; }" : "=r"(a) : "l"(p));
    return a;
}
__device__ __forceinline__ void ldsm4(uint32_t* r, uint32_t addr) {
    asm volatile("ldmatrix.sync.aligned.m8n8.x4.shared.b16 {%0,%1,%2,%3}, [%4];"
        : "=r"(r[0]), "=r"(r[1]), "=r"(r[2]), "=r"(r[3]) : "r"(addr));
}
__device__ __forceinline__ void mma16816(float* c, const uint32_t* a, const uint32_t* b) {
    asm volatile("mma.sync.aligned.m16n8k16.row.col.f32.bf16.bf16.f32 "
        "{%0,%1,%2,%3}, {%4,%5,%6,%7}, {%8,%9}, {%0,%1,%2,%3};"
        : "+f"(c[0]), "+f"(c[1]), "+f"(c[2]), "+f"(c[3])
        : "r"(a[0]), "r"(a[1]), "r"(a[2]), "r"(a[3]), "r"(b[0]), "r"(b[1]));
}
__device__ __forceinline__ uint32_t pack2(__nv_bfloat16 a, __nv_bfloat16 b) {
    return (uint32_t)__bfloat16_as_ushort(a) | ((uint32_t)__bfloat16_as_ushort(b) << 16);
}
__device__ __forceinline__ void cp16(uint32_t dst, const void* src, int sz) {
    asm volatile("cp.async.cg.shared.global [%0], [%1], 16, %2;"
                 :: "r"(dst), "l"(src), "r"(sz) : "memory");
}
#define CP_COMMIT asm volatile("cp.async.commit_group;" ::: "memory")
#define CP_WAIT1  asm volatile("cp.async.wait_group 1;" ::: "memory")

// ---- fp32 -> (hi,lo) bf16 split, elementwise (n % 4 == 0) ----
__global__ void split_kernel(const float* __restrict__ in,
                             __nv_bfloat16* __restrict__ hi,
                             __nv_bfloat16* __restrict__ lo, int n)
{
    int i = (blockIdx.x * blockDim.x + threadIdx.x) * 4;
    if (i >= n) return;
    float4 v = *(const float4*)(in + i);
    __nv_bfloat16 h0 = __float2bfloat16(v.x), h1 = __float2bfloat16(v.y);
    __nv_bfloat16 h2 = __float2bfloat16(v.z), h3 = __float2bfloat16(v.w);
    uint2 hw = make_uint2(pack2(h0, h1), pack2(h2, h3));
    uint2 lw = make_uint2(
        pack2(__float2bfloat16(v.x - __bfloat162float(h0)),
              __float2bfloat16(v.y - __bfloat162float(h1))),
        pack2(__float2bfloat16(v.z - __bfloat162float(h2)),
              __float2bfloat16(v.w - __bfloat162float(h3))));
    *(uint2*)(hi + i) = hw;
    *(uint2*)(lo + i) = lw;
}

// ================= bf16 HMMA GEMM, 3-stage cp.async pipeline =================
// SMEM stage: Ahi[128][32] @0, Alo @8192, Bhi @16384, Blo @24576 (bf16, 64B rows)
// Swizzle: chunk (r,g) -> col (g ^ ((r>>1)&3)); conflict-free ldmatrix loads.
#define STAGE_BYTES 32768
#define NSTAGES 3
#define GSMEM_BYTES (NSTAGES * STAGE_BYTES)
#define SWOFF(r, g) ((uint32_t)((r) * 64 + (((g) ^ (((r) >> 1) & 3)) * 16)))

// Y[N,M] = A[N,K] @ B[M,K]^T with A=Ahi+Alo, B=Bhi+Blo (drop lo*lo).
// K % 32 == 0 and K/32 >= 3; M % 128 == 0. Grid (ceil(N/128), M/128), 256 thr.
__global__ __launch_bounds__(256) void gemm_bf16(
    const __nv_bfloat16* __restrict__ Ahi, const __nv_bfloat16* __restrict__ Alo,
    const __nv_bfloat16* __restrict__ Bhi, const __nv_bfloat16* __restrict__ Blo,
    float* __restrict__ Y, int Nrows, int K, int Mout)
{
    extern __shared__ char smem[];
    const int tid = threadIdx.x, lane = tid & 31, wid = tid >> 5;
    const int wm = wid >> 2, wn = wid & 3;          // warp grid 2 x 4
    const int rowBase = blockIdx.x * 128, colBase = blockIdx.y * 128;
    const uint32_t sb = smem_u32(smem);

    float c[4][4][4];
#pragma unroll
    for (int i = 0; i < 4; i++)
#pragma unroll
        for (int j = 0; j < 4; j++)
#pragma unroll
            for (int q = 0; q < 4; q++) c[i][j][q] = 0.f;

    const int NC = K >> 5;

#define LOADST(BUF, K0) do {                                                   \
    uint32_t st = sb + (BUF) * STAGE_BYTES;                                    \
    _Pragma("unroll")                                                          \
    for (int it = 0; it < 2; it++) {                                           \
        int chunk = it * 256 + tid;                                            \
        int r = chunk >> 2, g = chunk & 3;                                     \
        uint32_t soff = SWOFF(r, g);                                           \
        int gr = rowBase + r;                                                  \
        int sz = (gr < Nrows) ? 16 : 0;                                        \
        int grc = gr < Nrows ? gr : (Nrows - 1);                               \
        cp16(st + soff,         Ahi + (size_t)grc * K + (K0) + g * 8, sz);     \
        cp16(st + 8192 + soff,  Alo + (size_t)grc * K + (K0) + g * 8, sz);     \
        cp16(st + 16384 + soff, Bhi + (size_t)(colBase + r) * K + (K0) + g * 8, 16); \
        cp16(st + 24576 + soff, Blo + (size_t)(colBase + r) * K + (K0) + g * 8, 16); \
    }                                                                          \
} while (0)

    const int lrow = lane & 15, lsel = lane >> 4;

#define COMPUTE(BUF) do {                                                      \
    uint32_t ab = sb + (BUF) * STAGE_BYTES;                                    \
    _Pragma("unroll")                                                          \
    for (int ks = 0; ks < 2; ks++) {                                           \
        int g = ks * 2 + lsel;                                                 \
        uint32_t ahi[4][4], alo[4][4];                                         \
        _Pragma("unroll")                                                      \
        for (int mt = 0; mt < 4; mt++) {                                       \
            int row = wm * 64 + mt * 16 + lrow;                                \
            uint32_t off = SWOFF(row, g);                                      \
            ldsm4(ahi[mt], ab + off);                                          \
            ldsm4(alo[mt], ab + 8192 + off);                                   \
        }                                                                      \
        uint32_t bhi[2][4], blo[2][4];                                         \
        _Pragma("unroll")                                                      \
        for (int bt = 0; bt < 2; bt++) {                                       \
            int row = wn * 32 + bt * 16 + lrow;                                \
            uint32_t off = SWOFF(row, g);                                      \
            ldsm4(bhi[bt], ab + 16384 + off);                                  \
            ldsm4(blo[bt], ab + 24576 + off);                                  \
        }                                                                      \
        _Pragma("unroll")                                                      \
        for (int mt = 0; mt < 4; mt++)                                         \
        _Pragma("unroll")                                                      \
        for (int nt = 0; nt < 4; nt++) {                                       \
            uint32_t bh[2] = { bhi[nt >> 1][nt & 1], bhi[nt >> 1][(nt & 1) + 2] }; \
            uint32_t bl[2] = { blo[nt >> 1][nt & 1], blo[nt >> 1][(nt & 1) + 2] }; \
            mma16816(c[mt][nt], ahi[mt], bh);                                  \
            mma16816(c[mt][nt], ahi[mt], bl);                                  \
            mma16816(c[mt][nt], alo[mt], bh);                                  \
        }                                                                      \
    }                                                                          \
} while (0)

    LOADST(0, 0);  CP_COMMIT;
    LOADST(1, 32); CP_COMMIT;

    for (int cc = 0; cc < NC; cc++) {
        CP_WAIT1;
        __syncthreads();
        int nx = cc + 2;
        if (nx < NC) LOADST(nx % 3, nx * 32);
        CP_COMMIT;
        COMPUTE(cc % 3);
    }

    // epilogue: C fragment -> Y (fp32)
#pragma unroll
    for (int mt = 0; mt < 4; mt++) {
        int r0 = rowBase + wm * 64 + mt * 16 + (lane >> 2);
        int r1 = r0 + 8;
#pragma unroll
        for (int nt = 0; nt < 4; nt++) {
            int col = colBase + wn * 32 + nt * 8 + (lane & 3) * 2;
            if (r0 < Nrows)
                *(float2*)(Y + (size_t)r0 * Mout + col) = make_float2(c[mt][nt][0], c[mt][nt][1]);
            if (r1 < Nrows)
                *(float2*)(Y + (size_t)r1 * Mout + col) = make_float2(c[mt][nt][2], c[mt][nt][3]);
        }
    }
}

// ================= graph / CSR machinery (unchanged, known good) =================
__global__ void detect_idx_kernel(const unsigned int* __restrict__ w) {
    int is32 = 0;
#pragma unroll
    for (int i = 1; i < 64; i += 2)
        if (w[i] != 0u) is32 = 1;
    g_is32 = is32;
}
__device__ __forceinline__ int edge_src(const void* ei, int E, int e) {
    return g_is32 ? ((const int*)ei)[e] : (int)((const long long*)ei)[e];
}
__device__ __forceinline__ int edge_dst(const void* ei, int E, int e) {
    return g_is32 ? ((const int*)ei)[E + e] : (int)((const long long*)ei)[E + e];
}
__global__ void hist_kernel(const void* __restrict__ ei, int E, int Nn, int* __restrict__ deg) {
    int e = blockIdx.x * blockDim.x + threadIdx.x;
    int EP = E + Nn;
    if (e >= EP) return;
    int dst = (e < E) ? edge_dst(ei, E, e) : (e - E);
    atomicAdd(&deg[dst], 1);
}
__global__ __launch_bounds__(1024) void scan_kernel(
    const int* __restrict__ deg, int* __restrict__ off, int* __restrict__ cur, int Nn)
{
    __shared__ int wsum[32];
    int tid = threadIdx.x, lane = tid & 31, wid = tid >> 5;
    int chunk = (Nn + 1023) >> 10;
    int start = min(tid * chunk, Nn), end = min(start + chunk, Nn);
    int s = 0;
    for (int i = start; i < end; i++) s += deg[i];
    int v = s;
#pragma unroll
    for (int o = 1; o < 32; o <<= 1) {
        int u = __shfl_up_sync(0xffffffffu, v, o);
        if (lane >= o) v += u;
    }
    if (lane == 31) wsum[wid] = v;
    __syncthreads();
    if (wid == 0) {
        int w = wsum[lane];
#pragma unroll
        for (int o = 1; o < 32; o <<= 1) {
            int u = __shfl_up_sync(0xffffffffu, w, o);
            if (lane >= o) w += u;
        }
        wsum[lane] = w;
    }
    __syncthreads();
    int incl = v + (wid ? wsum[wid - 1] : 0);
    int pre = incl - s;
    for (int i = start; i < end; i++) { off[i] = pre; cur[i] = pre; pre += deg[i]; }
    if (end == Nn) off[Nn] = pre;
}
__global__ void scatter_kernel(const void* __restrict__ ei, int E, int Nn,
                               int* __restrict__ cur, int* __restrict__ srcs)
{
    int e = blockIdx.x * blockDim.x + threadIdx.x;
    int EP = E + Nn;
    if (e >= EP) return;
    int src, dst;
    if (e < E) { src = edge_src(ei, E, e); dst = edge_dst(ei, E, e); }
    else       { src = e - E; dst = src; }
    int pos = atomicAdd(&cur[dst], 1);
    srcs[pos] = src;
}

// ---------------- attention coefficients ----------------
template<int H>
__global__ void sndn_kernel(const float* __restrict__ h,
                            const float* __restrict__ a_src, const float* __restrict__ a_dst,
                            float* __restrict__ sn, float* __restrict__ dn, int Nn)
{
    int wid = (blockIdx.x * blockDim.x + threadIdx.x) >> 5;
    int lane = threadIdx.x & 31;
    if (wid >= Nn * H) return;
    int n = wid / H, hh = wid - n * H;
    const float* row = h + (size_t)n * (H * 128) + hh * 128;
    float4 v  = *((const float4*)row + lane);
    float4 as = *((const float4*)(a_src + hh * 128) + lane);
    float4 ad = *((const float4*)(a_dst + hh * 128) + lane);
    float s = v.x * as.x + v.y * as.y + v.z * as.z + v.w * as.w;
    float d = v.x * ad.x + v.y * ad.y + v.z * ad.z + v.w * ad.w;
#pragma unroll
    for (int o = 16; o; o >>= 1) {
        s += __shfl_down_sync(0xffffffffu, s, o);
        d += __shfl_down_sync(0xffffffffu, d, o);
    }
    if (lane == 0) { sn[wid] = s; dn[wid] = d; }
}

// ---------------- fused GAT aggregation (H=4), bf16-split output ----------------
__global__ __launch_bounds__(128) void gat_agg_h4(
    const float* __restrict__ h, const float* __restrict__ sn,
    const float* __restrict__ dn, const int* __restrict__ off,
    const int* __restrict__ srcs, const float* __restrict__ bias,
    __nv_bfloat16* __restrict__ ohi, __nv_bfloat16* __restrict__ olo, int Nn)
{
    int n = blockIdx.x;
    int t = threadIdx.x, w = t >> 5, lane = t & 31;
    int beg = off[n], end = off[n + 1];
    float dn_w = dn[n * 4 + w];
    float den = 0.f;
    for (int i = beg + lane; i < end; i += 32) {
        float e = sn[srcs[i] * 4 + w] + dn_w;
        e = e > 0.f ? e : 0.2f * e;
        den += __expf(e);
    }
#pragma unroll
    for (int o = 16; o; o >>= 1) den += __shfl_xor_sync(0xffffffffu, den, o);
    float inv = 1.f / (den + 1e-16f);
    float4 acc = make_float4(0.f, 0.f, 0.f, 0.f);
    for (int i = beg; i < end; i++) {
        int s = srcs[i];
        float e = sn[s * 4 + w] + dn_w;
        e = e > 0.f ? e : 0.2f * e;
        float alpha = __expf(e) * inv;
        float4 v = *((const float4*)(h + (size_t)s * 512) + t);
        acc.x += alpha * v.x; acc.y += alpha * v.y;
        acc.z += alpha * v.z; acc.w += alpha * v.w;
    }
    float4 b = *((const float4*)bias + t);
    acc.x += b.x; acc.y += b.y; acc.z += b.z; acc.w += b.w;
    acc.x = acc.x > 0.f ? acc.x : expm1f(acc.x);
    acc.y = acc.y > 0.f ? acc.y : expm1f(acc.y);
    acc.z = acc.z > 0.f ? acc.z : expm1f(acc.z);
    acc.w = acc.w > 0.f ? acc.w : expm1f(acc.w);
    __nv_bfloat16 h0 = __float2bfloat16(acc.x), h1 = __float2bfloat16(acc.y);
    __nv_bfloat16 h2 = __float2bfloat16(acc.z), h3 = __float2bfloat16(acc.w);
    uint2 hw = make_uint2(pack2(h0, h1), pack2(h2, h3));
    uint2 lw = make_uint2(
        pack2(__float2bfloat16(acc.x - __bfloat162float(h0)),
              __float2bfloat16(acc.y - __bfloat162float(h1))),
        pack2(__float2bfloat16(acc.z - __bfloat162float(h2)),
              __float2bfloat16(acc.w - __bfloat162float(h3))));
    *(uint2*)(ohi + (size_t)n * 512 + t * 4) = hw;
    *(uint2*)(olo + (size_t)n * 512 + t * 4) = lw;
}

// ---------------- fused GAT aggregation (H=1), fp32 output ----------------
__global__ __launch_bounds__(128) void gat_agg_h1(
    const float* __restrict__ h, const float* __restrict__ sn,
    const float* __restrict__ dn, const int* __restrict__ off,
    const int* __restrict__ srcs, const float* __restrict__ bias,
    float* __restrict__ out, int Nn)
{
    int n = blockIdx.x;
    int t = threadIdx.x, lane = t & 31;
    int beg = off[n], end = off[n + 1];
    float dnv = dn[n];
    float den = 0.f;
    for (int i = beg + lane; i < end; i += 32) {
        float e = sn[srcs[i]] + dnv;
        e = e > 0.f ? e : 0.2f * e;
        den += __expf(e);
    }
#pragma unroll
    for (int o = 16; o; o >>= 1) den += __shfl_xor_sync(0xffffffffu, den, o);
    float inv = 1.f / (den + 1e-16f);
    float acc = 0.f;
    for (int i = beg; i < end; i++) {
        int s = srcs[i];
        float e = sn[s] + dnv;
        e = e > 0.f ? e : 0.2f * e;
        float alpha = __expf(e) * inv;
        acc += alpha * h[(size_t)s * 128 + t];
    }
    out[(size_t)n * 128 + t] = acc + bias[t];
}

// ---------------- allocation head ----------------
__global__ __launch_bounds__(64) void head_kernel(
    const float* __restrict__ emb, const float* __restrict__ Wh1,
    const float* __restrict__ bh1, const float* __restrict__ Wh2,
    const float* __restrict__ bh2, float* __restrict__ score, int Nn)
{
    int n = blockIdx.x;
    int t = threadIdx.x;
    __shared__ __align__(16) float se[128];
    __shared__ float sred2[2];
    ((float2*)se)[t] = ((const float2*)(emb + (size_t)n * 128))[t];
    __syncthreads();
    float z = bh1[t];
    const float* wrow = Wh1 + t * 128;
#pragma unroll 8
    for (int k = 0; k < 128; k++) z += se[k] * wrow[k];
    z = fmaxf(z, 0.f);
    float val = z * Wh2[t];
#pragma unroll
    for (int o = 16; o; o >>= 1) val += __shfl_down_sync(0xffffffffu, val, o);
    if ((t & 31) == 0) sred2[t >> 5] = val;
    __syncthreads();
    if (t == 0) {
        float s = sred2[0] + sred2[1] + bh2[0];
        score[n] = 1.f / (1.f + __expf(-s));
    }
}

// ---------------- driver ----------------
extern "C" void kernel_launch(void* const* d_in, const int* in_sizes, int n_in,
                              void* d_out, int out_size)
{
    const float* x      = (const float*)d_in[0];
    const void*  ei     = d_in[1];
    const float* W1     = (const float*)d_in[2];
    const float* a_src1 = (const float*)d_in[3];
    const float* a_dst1 = (const float*)d_in[4];
    const float* b1     = (const float*)d_in[5];
    const float* W2     = (const float*)d_in[6];
    const float* a_src2 = (const float*)d_in[7];
    const float* a_dst2 = (const float*)d_in[8];
    const float* b2     = (const float*)d_in[9];
    const float* W3     = (const float*)d_in[10];
    const float* a_src3 = (const float*)d_in[11];
    const float* a_dst3 = (const float*)d_in[12];
    const float* b3     = (const float*)d_in[13];
    const float* Wh1    = (const float*)d_in[14];
    const float* bh1    = (const float*)d_in[15];
    const float* Wh2    = (const float*)d_in[16];
    const float* bh2    = (const float*)d_in[17];

    int Nn = in_sizes[0] / 256;
    int E  = in_sizes[1] / 2;
    int EP = E + Nn;

    float *buf0, *sn, *dn;
    __nv_bfloat16 *ahi, *alo, *whi, *wlo;
    int *deg, *off, *cur, *srcs;
    cudaGetSymbolAddress((void**)&buf0, g_buf0);
    cudaGetSymbolAddress((void**)&ahi,  g_ahi);
    cudaGetSymbolAddress((void**)&alo,  g_alo);
    cudaGetSymbolAddress((void**)&whi,  g_whi);
    cudaGetSymbolAddress((void**)&wlo,  g_wlo);
    cudaGetSymbolAddress((void**)&sn,   g_sn);
    cudaGetSymbolAddress((void**)&dn,   g_dn);
    cudaGetSymbolAddress((void**)&deg,  g_deg);
    cudaGetSymbolAddress((void**)&off,  g_off);
    cudaGetSymbolAddress((void**)&cur,  g_cur);
    cudaGetSymbolAddress((void**)&srcs, g_csr_src);

    float* out_emb   = (float*)d_out;
    float* out_score = (float*)d_out + (size_t)Nn * 128;

    cudaFuncSetAttribute(gemm_bf16, cudaFuncAttributeMaxDynamicSharedMemorySize, GSMEM_BYTES);

    // ---- CSR build ----
    detect_idx_kernel<<<1, 1>>>((const unsigned int*)ei);
    cudaMemsetAsync(deg, 0, Nn * sizeof(int));
    hist_kernel<<<(EP + 255) / 256, 256>>>(ei, E, Nn, deg);
    scan_kernel<<<1, 1024>>>(deg, off, cur, Nn);
    scatter_kernel<<<(EP + 255) / 256, 256>>>(ei, E, Nn, cur, srcs);

    int rowTiles = (Nn + 127) / 128;

    // ---- Layer 1: 256 -> 512 ----
    split_kernel<<<(Nn * 256 / 4 + 255) / 256, 256>>>(x, ahi, alo, Nn * 256);
    split_kernel<<<(512 * 256 / 4 + 255) / 256, 256>>>(W1, whi, wlo, 512 * 256);
    gemm_bf16<<<dim3(rowTiles, 4), 256, GSMEM_BYTES>>>(ahi, alo, whi, wlo, buf0, Nn, 256, 512);
    sndn_kernel<4><<<(Nn * 4 * 32 + 255) / 256, 256>>>(buf0, a_src1, a_dst1, sn, dn, Nn);
    gat_agg_h4<<<Nn, 128>>>(buf0, sn, dn, off, srcs, b1, ahi, alo, Nn);

    // ---- Layer 2: 512 -> 512 ----
    split_kernel<<<(512 * 512 / 4 + 255) / 256, 256>>>(W2, whi, wlo, 512 * 512);
    gemm_bf16<<<dim3(rowTiles, 4), 256, GSMEM_BYTES>>>(ahi, alo, whi, wlo, buf0, Nn, 512, 512);
    sndn_kernel<4><<<(Nn * 4 * 32 + 255) / 256, 256>>>(buf0, a_src2, a_dst2, sn, dn, Nn);
    gat_agg_h4<<<Nn, 128>>>(buf0, sn, dn, off, srcs, b2, ahi, alo, Nn);

    // ---- Layer 3: 512 -> 128 ----
    split_kernel<<<(128 * 512 / 4 + 255) / 256, 256>>>(W3, whi, wlo, 128 * 512);
    gemm_bf16<<<dim3(rowTiles, 1), 256, GSMEM_BYTES>>>(ahi, alo, whi, wlo, buf0, Nn, 512, 128);
    sndn_kernel<1><<<(Nn * 32 + 255) / 256, 256>>>(buf0, a_src3, a_dst3, sn, dn, Nn);
    gat_agg_h1<<<Nn, 128>>>(buf0, sn, dn, off, srcs, b3, out_emb, Nn);

    // ---- Allocation head ----
    head_kernel<<<Nn, 64>>>(out_emb, Wh1, bh1, Wh2, bh2, out_score, Nn);
}